// round 1
// baseline (speedup 1.0000x reference)
#include <cuda_runtime.h>
#include <math.h>

#define T_DIM 8192
#define D_DIM 128
#define BM 64
#define BN 64
#define NTH 256
#define QS_STRIDE (D_DIM + 4)   /* 132 */
#define KT_STRIDE (BN + 4)      /* 68  */
#define PS_STRIDE (BN + 4)      /* 68  */
#define NBLOCKS (T_DIM / BM)    /* 128 */

#define SMEM_FLOATS (BM*QS_STRIDE + D_DIM*KT_STRIDE + BN*D_DIM + BM*PS_STRIDE + BN)
#define SMEM_BYTES (SMEM_FLOATS * 4)

__device__ float g_qbias[T_DIM];
__device__ float g_hpart[NBLOCKS * D_DIM];
__device__ float g_h[D_DIM];

// ---------------------------------------------------------------------------
// K0: per-key bias  qbias[j] = question[j] . w_q
// ---------------------------------------------------------------------------
__global__ void qbias_kernel(const float* __restrict__ x, const float* __restrict__ kern) {
    int j = blockIdx.x * 8 + (threadIdx.x >> 5);
    int lane = threadIdx.x & 31;
    const float* q  = x + (size_t)T_DIM * D_DIM + (size_t)j * D_DIM;
    const float* wq = kern + D_DIM;
    float s = q[lane]      * wq[lane]
            + q[lane + 32] * wq[lane + 32]
            + q[lane + 64] * wq[lane + 64]
            + q[lane + 96] * wq[lane + 96];
    #pragma unroll
    for (int off = 16; off; off >>= 1) s += __shfl_xor_sync(0xffffffffu, s, off);
    if (lane == 0) g_qbias[j] = s;
}

// ---------------------------------------------------------------------------
// K1: flash attention (fp32 SIMT).  Writes out columns [0,384):
//   [0:128)=context, [128:256)=U_A, [256:384)=context*U_A.
// Also emits per-block partial of h = sum_i (1/l_i) * context[i,:].
// ---------------------------------------------------------------------------
__global__ void __launch_bounds__(NTH, 1)
flash_kernel(const float* __restrict__ x, const float* __restrict__ kern,
             float* __restrict__ out)
{
    extern __shared__ float sm[];
    float* Qs = sm;                              // [BM][QS_STRIDE]  Q' = ctx*w_m
    float* Kt = Qs + BM * QS_STRIDE;             // [D][KT_STRIDE]   K transposed
    float* Ks = Kt + D_DIM * KT_STRIDE;          // [BN][D]          K row-major (=V)
    float* Ps = Ks + BN * D_DIM;                 // [BM][PS_STRIDE]  exp(scores)
    float* qb = Ps + BM * PS_STRIDE;             // [BN]             key bias tile

    const float* ctx = x;
    const float* qst = x + (size_t)T_DIM * D_DIM;
    const float* wm  = kern + 2 * D_DIM;

    const int tid = threadIdx.x;
    const int tx  = tid & 15;     // key / d-column group
    const int ty  = tid >> 4;     // row group
    const int row0 = blockIdx.x * BM;

    // ---- load Q' tile (context * w_m), float4, coalesced ----
    for (int i = tid; i < BM * (D_DIM / 4); i += NTH) {
        int r  = i >> 5;
        int d4 = (i & 31) << 2;
        float4 v = *(const float4*)&ctx[(row0 + r) * D_DIM + d4];
        float4 w = *(const float4*)&wm[d4];
        v.x *= w.x; v.y *= w.y; v.z *= w.z; v.w *= w.w;
        *(float4*)&Qs[r * QS_STRIDE + d4] = v;
    }

    float m_r[4], l_r[4], acc[4][8];
    #pragma unroll
    for (int r = 0; r < 4; ++r) {
        m_r[r] = -INFINITY; l_r[r] = 0.f;
        #pragma unroll
        for (int c = 0; c < 8; ++c) acc[r][c] = 0.f;
    }

    for (int t = 0; t < T_DIM / BN; ++t) {
        __syncthreads();
        const int k0 = t * BN;
        // ---- load K tile into both layouts (scalar for conflict-free transpose) ----
        for (int i = tid; i < BN * D_DIM; i += NTH) {
            int key = i >> 7;
            int d   = i & 127;
            float v = qst[(k0 + key) * D_DIM + d];
            Ks[key * D_DIM + d]    = v;
            Kt[d * KT_STRIDE + key] = v;
        }
        if (tid < BN) qb[tid] = g_qbias[k0 + tid];
        __syncthreads();

        // ---- GEMM1: S = Q' @ K^T  (4 rows x 4 keys per thread) ----
        float s[4][4];
        #pragma unroll
        for (int r = 0; r < 4; ++r)
            #pragma unroll
            for (int c = 0; c < 4; ++c) s[r][c] = 0.f;

        #pragma unroll 4
        for (int d4 = 0; d4 < D_DIM; d4 += 4) {
            float4 b0 = *(const float4*)&Kt[(d4 + 0) * KT_STRIDE + tx * 4];
            float4 b1 = *(const float4*)&Kt[(d4 + 1) * KT_STRIDE + tx * 4];
            float4 b2 = *(const float4*)&Kt[(d4 + 2) * KT_STRIDE + tx * 4];
            float4 b3 = *(const float4*)&Kt[(d4 + 3) * KT_STRIDE + tx * 4];
            #pragma unroll
            for (int r = 0; r < 4; ++r) {
                float4 a = *(const float4*)&Qs[(ty * 4 + r) * QS_STRIDE + d4];
                s[r][0] += a.x * b0.x + a.y * b1.x + a.z * b2.x + a.w * b3.x;
                s[r][1] += a.x * b0.y + a.y * b1.y + a.z * b2.y + a.w * b3.y;
                s[r][2] += a.x * b0.z + a.y * b1.z + a.z * b2.z + a.w * b3.z;
                s[r][3] += a.x * b0.w + a.y * b1.w + a.z * b2.w + a.w * b3.w;
            }
        }

        // ---- bias + online softmax ----
        float4 qv = *(const float4*)&qb[tx * 4];
        #pragma unroll
        for (int r = 0; r < 4; ++r) {
            s[r][0] += qv.x; s[r][1] += qv.y; s[r][2] += qv.z; s[r][3] += qv.w;
            float mx = fmaxf(fmaxf(s[r][0], s[r][1]), fmaxf(s[r][2], s[r][3]));
            mx = fmaxf(mx, __shfl_xor_sync(0xffffffffu, mx, 8));
            mx = fmaxf(mx, __shfl_xor_sync(0xffffffffu, mx, 4));
            mx = fmaxf(mx, __shfl_xor_sync(0xffffffffu, mx, 2));
            mx = fmaxf(mx, __shfl_xor_sync(0xffffffffu, mx, 1));
            float mnew  = fmaxf(m_r[r], mx);
            float alpha = __expf(m_r[r] - mnew);
            m_r[r] = mnew;
            float p0 = __expf(s[r][0] - mnew);
            float p1 = __expf(s[r][1] - mnew);
            float p2 = __expf(s[r][2] - mnew);
            float p3 = __expf(s[r][3] - mnew);
            float rs = (p0 + p1) + (p2 + p3);
            rs += __shfl_xor_sync(0xffffffffu, rs, 8);
            rs += __shfl_xor_sync(0xffffffffu, rs, 4);
            rs += __shfl_xor_sync(0xffffffffu, rs, 2);
            rs += __shfl_xor_sync(0xffffffffu, rs, 1);
            l_r[r] = l_r[r] * alpha + rs;
            #pragma unroll
            for (int c = 0; c < 8; ++c) acc[r][c] *= alpha;
            *(float4*)&Ps[(ty * 4 + r) * PS_STRIDE + tx * 4] = make_float4(p0, p1, p2, p3);
        }
        __syncwarp();   // P rows are produced and consumed within the same half-warp

        // ---- GEMM2: acc += P @ V  (V = Ks) ----
        #pragma unroll 4
        for (int k4 = 0; k4 < BN; k4 += 4) {
            float4 v00 = *(const float4*)&Ks[(k4 + 0) * D_DIM + tx * 8];
            float4 v01 = *(const float4*)&Ks[(k4 + 0) * D_DIM + tx * 8 + 4];
            float4 v10 = *(const float4*)&Ks[(k4 + 1) * D_DIM + tx * 8];
            float4 v11 = *(const float4*)&Ks[(k4 + 1) * D_DIM + tx * 8 + 4];
            float4 v20 = *(const float4*)&Ks[(k4 + 2) * D_DIM + tx * 8];
            float4 v21 = *(const float4*)&Ks[(k4 + 2) * D_DIM + tx * 8 + 4];
            float4 v30 = *(const float4*)&Ks[(k4 + 3) * D_DIM + tx * 8];
            float4 v31 = *(const float4*)&Ks[(k4 + 3) * D_DIM + tx * 8 + 4];
            #pragma unroll
            for (int r = 0; r < 4; ++r) {
                float4 a = *(const float4*)&Ps[(ty * 4 + r) * PS_STRIDE + k4];
                acc[r][0] += a.x * v00.x + a.y * v10.x + a.z * v20.x + a.w * v30.x;
                acc[r][1] += a.x * v00.y + a.y * v10.y + a.z * v20.y + a.w * v30.y;
                acc[r][2] += a.x * v00.z + a.y * v10.z + a.z * v20.z + a.w * v30.z;
                acc[r][3] += a.x * v00.w + a.y * v10.w + a.z * v20.w + a.w * v30.w;
                acc[r][4] += a.x * v01.x + a.y * v11.x + a.z * v21.x + a.w * v31.x;
                acc[r][5] += a.x * v01.y + a.y * v11.y + a.z * v21.y + a.w * v31.y;
                acc[r][6] += a.x * v01.z + a.y * v11.z + a.z * v21.z + a.w * v31.z;
                acc[r][7] += a.x * v01.w + a.y * v11.w + a.z * v21.w + a.w * v31.w;
            }
        }
    }

    // ---- epilogue: normalize, write G cols [0,384), accumulate h partials ----
    __syncthreads();
    float hp[8];
    #pragma unroll
    for (int c = 0; c < 8; ++c) hp[c] = 0.f;

    #pragma unroll
    for (int r = 0; r < 4; ++r) {
        int row = row0 + ty * 4 + r;
        float inv = 1.0f / l_r[r];          // == b[row] = max_j A[row,j]
        float4 c0 = *(const float4*)&ctx[row * D_DIM + tx * 8];
        float4 c1 = *(const float4*)&ctx[row * D_DIM + tx * 8 + 4];
        float4 u0 = make_float4(acc[r][0] * inv, acc[r][1] * inv, acc[r][2] * inv, acc[r][3] * inv);
        float4 u1 = make_float4(acc[r][4] * inv, acc[r][5] * inv, acc[r][6] * inv, acc[r][7] * inv);
        float* orow = out + (size_t)row * (4 * D_DIM);
        *(float4*)&orow[tx * 8]               = c0;
        *(float4*)&orow[tx * 8 + 4]           = c1;
        *(float4*)&orow[D_DIM + tx * 8]       = u0;
        *(float4*)&orow[D_DIM + tx * 8 + 4]   = u1;
        *(float4*)&orow[2 * D_DIM + tx * 8]     = make_float4(c0.x * u0.x, c0.y * u0.y, c0.z * u0.z, c0.w * u0.w);
        *(float4*)&orow[2 * D_DIM + tx * 8 + 4] = make_float4(c1.x * u1.x, c1.y * u1.y, c1.z * u1.z, c1.w * u1.w);
        hp[0] += inv * c0.x; hp[1] += inv * c0.y; hp[2] += inv * c0.z; hp[3] += inv * c0.w;
        hp[4] += inv * c1.x; hp[5] += inv * c1.y; hp[6] += inv * c1.z; hp[7] += inv * c1.w;
    }

    float* stage = Ps;   // reuse: [16][128]
    *(float4*)&stage[ty * D_DIM + tx * 8]     = make_float4(hp[0], hp[1], hp[2], hp[3]);
    *(float4*)&stage[ty * D_DIM + tx * 8 + 4] = make_float4(hp[4], hp[5], hp[6], hp[7]);
    __syncthreads();
    if (tid < D_DIM) {
        float ssum = 0.f;
        #pragma unroll
        for (int yy = 0; yy < 16; ++yy) ssum += stage[yy * D_DIM + tid];
        g_hpart[blockIdx.x * D_DIM + tid] = ssum;
    }
}

// ---------------------------------------------------------------------------
// K2: deterministic reduction of per-block h partials
// ---------------------------------------------------------------------------
__global__ void hreduce_kernel() {
    int d = threadIdx.x;
    float s = 0.f;
    for (int b = 0; b < NBLOCKS; ++b) s += g_hpart[b * D_DIM + d];
    g_h[d] = s;
}

// ---------------------------------------------------------------------------
// K3: out cols [384,512) = context * h
// ---------------------------------------------------------------------------
__global__ void hwrite_kernel(const float* __restrict__ x, float* __restrict__ out) {
    int idx = blockIdx.x * blockDim.x + threadIdx.x;  // float4 index
    int row = idx >> 5;
    int dq  = idx & 31;
    float4 c = ((const float4*)x)[(size_t)row * 32 + dq];
    float4 h = ((const float4*)g_h)[dq];
    ((float4*)out)[(size_t)row * 128 + 96 + dq] =
        make_float4(c.x * h.x, c.y * h.y, c.z * h.z, c.w * h.w);
}

// ---------------------------------------------------------------------------
extern "C" void kernel_launch(void* const* d_in, const int* in_sizes, int n_in,
                              void* d_out, int out_size) {
    const float* x    = (const float*)d_in[0];   // (2,1,8192,128) fp32
    const float* kern = (const float*)d_in[1];   // (384,) fp32
    float* out = (float*)d_out;                  // (8192,512) fp32

    cudaFuncSetAttribute(flash_kernel, cudaFuncAttributeMaxDynamicSharedMemorySize, SMEM_BYTES);

    qbias_kernel<<<T_DIM / 8, 256>>>(x, kern);
    flash_kernel<<<NBLOCKS, NTH, SMEM_BYTES>>>(x, kern, out);
    hreduce_kernel<<<1, D_DIM>>>();
    hwrite_kernel<<<(T_DIM * D_DIM / 4) / 256, 256>>>(x, out);
}

// round 3
// speedup vs baseline: 3.3542x; 3.3542x over previous
#include <cuda_runtime.h>
#include <cuda_bf16.h>
#include <math.h>
#include <stdint.h>

#define T_DIM 8192
#define D_DIM 128
#define BM 128
#define BN 64
#define NSPLIT 4
#define KEYS_PER_SPLIT (T_DIM / NSPLIT)   /* 2048 */
#define NTILES (KEYS_PER_SPLIT / BN)      /* 32   */
#define NTH 128

/* smem byte offsets: K hi/lo [64][128]bf16 swizzled, Q hi/lo [128][128]bf16 */
#define OFF_KH 0
#define OFF_KL 16384
#define OFF_QH 32768
#define OFF_QL 65536
#define OFF_QB 98304
#define SMEM_SZ 98816

__device__ float  g_qbias[T_DIM];
__device__ float  g_O[NSPLIT * T_DIM * D_DIM];
__device__ float2 g_ml[NSPLIT * T_DIM];
__device__ float  g_b[T_DIM];
__device__ float  g_hpart[64 * D_DIM];
__device__ float  g_h[D_DIM];

__device__ __forceinline__ uint32_t smem_u32(const void* p) {
    uint32_t a;
    asm("{ .reg .u64 t; cvta.to.shared.u64 t, %1; cvt.u32.u64 %0, t; }" : "=r"(a) : "l"(p));
    return a;
}

/* split a pair of floats into bf16 hi + bf16 residual lo, packed */
__device__ __forceinline__ void split2(float a, float b, uint32_t& hi, uint32_t& lo) {
    __nv_bfloat16 ha = __float2bfloat16(a), hb = __float2bfloat16(b);
    __nv_bfloat16 la = __float2bfloat16(a - __bfloat162float(ha));
    __nv_bfloat16 lb = __float2bfloat16(b - __bfloat162float(hb));
    __nv_bfloat162 H, L;
    H.x = ha; H.y = hb;  L.x = la; L.y = lb;
    hi = *(uint32_t*)&H;  lo = *(uint32_t*)&L;
}

#define LDSM4(r, addr) \
    asm volatile("ldmatrix.sync.aligned.m8n8.x4.shared.b16 {%0,%1,%2,%3}, [%4];" \
        : "=r"((r)[0]), "=r"((r)[1]), "=r"((r)[2]), "=r"((r)[3]) : "r"(addr))
#define LDSM4T(r, addr) \
    asm volatile("ldmatrix.sync.aligned.m8n8.x4.trans.shared.b16 {%0,%1,%2,%3}, [%4];" \
        : "=r"((r)[0]), "=r"((r)[1]), "=r"((r)[2]), "=r"((r)[3]) : "r"(addr))
#define MMA(c, a, b) \
    asm volatile("mma.sync.aligned.m16n8k16.row.col.f32.bf16.bf16.f32 " \
        "{%0,%1,%2,%3}, {%4,%5,%6,%7}, {%8,%9}, {%0,%1,%2,%3};" \
        : "+f"((c)[0]), "+f"((c)[1]), "+f"((c)[2]), "+f"((c)[3]) \
        : "r"((a)[0]), "r"((a)[1]), "r"((a)[2]), "r"((a)[3]), "r"((b)[0]), "r"((b)[1]))

/* ================= K0: qbias[j] = question[j] . w_q ================= */
__global__ void qbias_kernel(const float* __restrict__ x, const float* __restrict__ kern) {
    int j = blockIdx.x * 8 + (threadIdx.x >> 5);
    int lane = threadIdx.x & 31;
    const float* q  = x + (size_t)T_DIM * D_DIM + (size_t)j * D_DIM;
    const float* wq = kern + D_DIM;
    float s = q[lane] * wq[lane] + q[lane + 32] * wq[lane + 32]
            + q[lane + 64] * wq[lane + 64] + q[lane + 96] * wq[lane + 96];
    #pragma unroll
    for (int off = 16; off; off >>= 1) s += __shfl_xor_sync(0xffffffffu, s, off);
    if (lane == 0) g_qbias[j] = s;
}

/* ================= K1: HMMA flash (split-K over keys) ================= */
__global__ void __launch_bounds__(NTH, 2)
flash_kernel(const float* __restrict__ x, const float* __restrict__ kern)
{
    extern __shared__ char smem[];
    const uint32_t sb = smem_u32(smem);
    float* qb = (float*)(smem + OFF_QB);

    const int tid  = threadIdx.x;
    const int lane = tid & 31;
    const int w    = tid >> 5;
    const int rowblk = blockIdx.x >> 2;
    const int split  = blockIdx.x & 3;
    const int row0 = rowblk * BM;

    const float* ctx = x;
    const float* qst = x + (size_t)T_DIM * D_DIM;
    const float* wm  = kern + 2 * D_DIM;

    /* ---- prologue: Q' = ctx*w_m → bf16 hi/lo, swizzled smem ---- */
    #pragma unroll
    for (int i = 0; i < 16; ++i) {
        int idx = tid + i * NTH;
        int row = idx >> 4, ch = idx & 15;
        const float* src = ctx + (size_t)(row0 + row) * D_DIM + ch * 8;
        float4 v0 = *(const float4*)src, v1 = *(const float4*)(src + 4);
        float4 w0 = *(const float4*)&wm[ch * 8], w1 = *(const float4*)&wm[ch * 8 + 4];
        v0.x *= w0.x; v0.y *= w0.y; v0.z *= w0.z; v0.w *= w0.w;
        v1.x *= w1.x; v1.y *= w1.y; v1.z *= w1.z; v1.w *= w1.w;
        uint32_t h0, l0, h1, l1, h2, l2, h3, l3;
        split2(v0.x, v0.y, h0, l0); split2(v0.z, v0.w, h1, l1);
        split2(v1.x, v1.y, h2, l2); split2(v1.z, v1.w, h3, l3);
        uint32_t off = row * 256 + ((ch ^ (row & 7)) << 4);
        *(uint4*)(smem + OFF_QH + off) = make_uint4(h0, h1, h2, h3);
        *(uint4*)(smem + OFF_QL + off) = make_uint4(l0, l1, l2, l3);
    }

    float O[2][16][4];
    float m_r[2][2], l_r[2][2];
    #pragma unroll
    for (int rb = 0; rb < 2; ++rb) {
        m_r[rb][0] = -INFINITY; m_r[rb][1] = -INFINITY;
        l_r[rb][0] = 0.f;       l_r[rb][1] = 0.f;
        #pragma unroll
        for (int nt = 0; nt < 16; ++nt)
            #pragma unroll
            for (int c = 0; c < 4; ++c) O[rb][nt][c] = 0.f;
    }

    const int m0 = w * 32;
    /* lane-invariant pieces of ldmatrix addressing */
    const int a_row  = (lane & 15);            /* + m0 + rb*16 */
    const int a_csel = (lane >> 4);
    const int b1_key = ((lane >> 4) << 3) + (lane & 7);  /* + np*16 */
    const int b1_cs  = ((lane >> 3) & 1);
    const int b2_key = ((lane >> 3) & 1) * 8 + (lane & 7); /* + kt2*16 */
    const int b2_cs  = (lane >> 4);

    for (int t = 0; t < NTILES; ++t) {
        __syncthreads();   /* prior tile's reads done */
        const int kbase = split * KEYS_PER_SPLIT + t * BN;
        /* ---- load + split-convert K tile (64x128) into Kh/Kl ---- */
        #pragma unroll
        for (int i = 0; i < 8; ++i) {
            int idx = tid + i * NTH;
            int row = idx >> 4, ch = idx & 15;
            const float* src = qst + (size_t)(kbase + row) * D_DIM + ch * 8;
            float4 v0 = *(const float4*)src, v1 = *(const float4*)(src + 4);
            uint32_t h0, l0, h1, l1, h2, l2, h3, l3;
            split2(v0.x, v0.y, h0, l0); split2(v0.z, v0.w, h1, l1);
            split2(v1.x, v1.y, h2, l2); split2(v1.z, v1.w, h3, l3);
            uint32_t off = row * 256 + ((ch ^ (row & 7)) << 4);
            *(uint4*)(smem + OFF_KH + off) = make_uint4(h0, h1, h2, h3);
            *(uint4*)(smem + OFF_KL + off) = make_uint4(l0, l1, l2, l3);
        }
        if (tid < BN) qb[tid] = g_qbias[kbase + tid];
        __syncthreads();

        /* ---- GEMM1: S = Qh*Kh + Ql*Kh + Qh*Kl ---- */
        float S[2][8][4];
        #pragma unroll
        for (int rb = 0; rb < 2; ++rb)
            #pragma unroll
            for (int nt = 0; nt < 8; ++nt)
                #pragma unroll
                for (int c = 0; c < 4; ++c) S[rb][nt][c] = 0.f;

        #pragma unroll
        for (int kt = 0; kt < 8; ++kt) {
            uint32_t bh[4][4];
            #pragma unroll
            for (int np = 0; np < 4; ++np) {
                int key = np * 16 + b1_key;
                int ch  = kt * 2 + b1_cs;
                LDSM4(bh[np], sb + OFF_KH + key * 256 + ((ch ^ (key & 7)) << 4));
            }
            uint32_t aQ[2][4];
            #pragma unroll
            for (int rb = 0; rb < 2; ++rb) {
                int row = m0 + rb * 16 + a_row;
                int ch  = kt * 2 + a_csel;
                LDSM4(aQ[rb], sb + OFF_QH + row * 256 + ((ch ^ (row & 7)) << 4));
            }
            #pragma unroll
            for (int rb = 0; rb < 2; ++rb)
                #pragma unroll
                for (int np = 0; np < 4; ++np) {
                    MMA(S[rb][2 * np],     aQ[rb], &bh[np][0]);
                    MMA(S[rb][2 * np + 1], aQ[rb], &bh[np][2]);
                }
            uint32_t aL[2][4];
            #pragma unroll
            for (int rb = 0; rb < 2; ++rb) {
                int row = m0 + rb * 16 + a_row;
                int ch  = kt * 2 + a_csel;
                LDSM4(aL[rb], sb + OFF_QL + row * 256 + ((ch ^ (row & 7)) << 4));
            }
            #pragma unroll
            for (int rb = 0; rb < 2; ++rb)
                #pragma unroll
                for (int np = 0; np < 4; ++np) {
                    MMA(S[rb][2 * np],     aL[rb], &bh[np][0]);
                    MMA(S[rb][2 * np + 1], aL[rb], &bh[np][2]);
                }
            /* reload B from Kl, reuse Qh frags */
            #pragma unroll
            for (int np = 0; np < 4; ++np) {
                int key = np * 16 + b1_key;
                int ch  = kt * 2 + b1_cs;
                LDSM4(bh[np], sb + OFF_KL + key * 256 + ((ch ^ (key & 7)) << 4));
            }
            #pragma unroll
            for (int rb = 0; rb < 2; ++rb) {
                int row = m0 + rb * 16 + a_row;
                int ch  = kt * 2 + a_csel;
                LDSM4(aQ[rb], sb + OFF_QH + row * 256 + ((ch ^ (row & 7)) << 4));
            }
            #pragma unroll
            for (int rb = 0; rb < 2; ++rb)
                #pragma unroll
                for (int np = 0; np < 4; ++np) {
                    MMA(S[rb][2 * np],     aQ[rb], &bh[np][0]);
                    MMA(S[rb][2 * np + 1], aQ[rb], &bh[np][2]);
                }
        }

        /* ---- online softmax (per-thread rows: r, r+8 in each rowblock) ---- */
        float qv[16];
        #pragma unroll
        for (int i = 0; i < 8; ++i) {
            float2 tq = *(const float2*)&qb[i * 8 + (lane & 3) * 2];
            qv[2 * i] = tq.x; qv[2 * i + 1] = tq.y;
        }
        uint32_t P[2][8][2];
        #pragma unroll
        for (int rb = 0; rb < 2; ++rb) {
            float mx0 = -INFINITY, mx1 = -INFINITY;
            #pragma unroll
            for (int nt = 0; nt < 8; ++nt) {
                S[rb][nt][0] += qv[2 * nt]; S[rb][nt][1] += qv[2 * nt + 1];
                S[rb][nt][2] += qv[2 * nt]; S[rb][nt][3] += qv[2 * nt + 1];
                mx0 = fmaxf(mx0, fmaxf(S[rb][nt][0], S[rb][nt][1]));
                mx1 = fmaxf(mx1, fmaxf(S[rb][nt][2], S[rb][nt][3]));
            }
            mx0 = fmaxf(mx0, __shfl_xor_sync(0xffffffffu, mx0, 1));
            mx0 = fmaxf(mx0, __shfl_xor_sync(0xffffffffu, mx0, 2));
            mx1 = fmaxf(mx1, __shfl_xor_sync(0xffffffffu, mx1, 1));
            mx1 = fmaxf(mx1, __shfl_xor_sync(0xffffffffu, mx1, 2));
            float mn0 = fmaxf(m_r[rb][0], mx0), mn1 = fmaxf(m_r[rb][1], mx1);
            float al0 = __expf(m_r[rb][0] - mn0), al1 = __expf(m_r[rb][1] - mn1);
            m_r[rb][0] = mn0; m_r[rb][1] = mn1;
            float ls0 = 0.f, ls1 = 0.f;
            #pragma unroll
            for (int nt = 0; nt < 8; ++nt) {
                float p0 = __expf(S[rb][nt][0] - mn0);
                float p1 = __expf(S[rb][nt][1] - mn0);
                float p2 = __expf(S[rb][nt][2] - mn1);
                float p3 = __expf(S[rb][nt][3] - mn1);
                __nv_bfloat162 b01, b23;
                b01.x = __float2bfloat16(p0); b01.y = __float2bfloat16(p1);
                b23.x = __float2bfloat16(p2); b23.y = __float2bfloat16(p3);
                /* l from ROUNDED P for O/l consistency */
                ls0 += __bfloat162float(b01.x) + __bfloat162float(b01.y);
                ls1 += __bfloat162float(b23.x) + __bfloat162float(b23.y);
                P[rb][nt][0] = *(uint32_t*)&b01;
                P[rb][nt][1] = *(uint32_t*)&b23;
            }
            ls0 += __shfl_xor_sync(0xffffffffu, ls0, 1);
            ls0 += __shfl_xor_sync(0xffffffffu, ls0, 2);
            ls1 += __shfl_xor_sync(0xffffffffu, ls1, 1);
            ls1 += __shfl_xor_sync(0xffffffffu, ls1, 2);
            l_r[rb][0] = l_r[rb][0] * al0 + ls0;
            l_r[rb][1] = l_r[rb][1] * al1 + ls1;
            #pragma unroll
            for (int nt = 0; nt < 16; ++nt) {
                O[rb][nt][0] *= al0; O[rb][nt][1] *= al0;
                O[rb][nt][2] *= al1; O[rb][nt][3] *= al1;
            }
        }

        /* ---- GEMM2: O += P*Vh + P*Vl  (B = ldmatrix.trans of K tiles) ---- */
        #pragma unroll
        for (int kt2 = 0; kt2 < 4; ++kt2) {
            uint32_t aP[2][4];
            #pragma unroll
            for (int rb = 0; rb < 2; ++rb) {
                aP[rb][0] = P[rb][2 * kt2][0];
                aP[rb][1] = P[rb][2 * kt2][1];
                aP[rb][2] = P[rb][2 * kt2 + 1][0];
                aP[rb][3] = P[rb][2 * kt2 + 1][1];
            }
            const int key = kt2 * 16 + b2_key;
            const uint32_t krow = key * 256 + sb;
            #pragma unroll
            for (int dp = 0; dp < 8; ++dp) {
                uint32_t bv[4];
                int ch = dp * 2 + b2_cs;
                LDSM4T(bv, krow + OFF_KH + ((ch ^ (key & 7)) << 4));
                #pragma unroll
                for (int rb = 0; rb < 2; ++rb) {
                    MMA(O[rb][2 * dp],     aP[rb], &bv[0]);
                    MMA(O[rb][2 * dp + 1], aP[rb], &bv[2]);
                }
            }
            #pragma unroll
            for (int dp = 0; dp < 8; ++dp) {
                uint32_t bv[4];
                int ch = dp * 2 + b2_cs;
                LDSM4T(bv, krow + OFF_KL + ((ch ^ (key & 7)) << 4));
                #pragma unroll
                for (int rb = 0; rb < 2; ++rb) {
                    MMA(O[rb][2 * dp],     aP[rb], &bv[0]);
                    MMA(O[rb][2 * dp + 1], aP[rb], &bv[2]);
                }
            }
        }
    }

    /* ---- epilogue: write O frags + (m,l) per row ---- */
    #pragma unroll
    for (int rb = 0; rb < 2; ++rb) {
        int r1 = row0 + m0 + rb * 16 + (lane >> 2);
        int r2 = r1 + 8;
        if ((lane & 3) == 0) {
            g_ml[(size_t)split * T_DIM + r1] = make_float2(m_r[rb][0], l_r[rb][0]);
            g_ml[(size_t)split * T_DIM + r2] = make_float2(m_r[rb][1], l_r[rb][1]);
        }
        float* o1 = g_O + ((size_t)split * T_DIM + r1) * D_DIM + (lane & 3) * 2;
        float* o2 = g_O + ((size_t)split * T_DIM + r2) * D_DIM + (lane & 3) * 2;
        #pragma unroll
        for (int nt = 0; nt < 16; ++nt) {
            *(float2*)(o1 + nt * 8) = make_float2(O[rb][nt][0], O[rb][nt][1]);
            *(float2*)(o2 + nt * 8) = make_float2(O[rb][nt][2], O[rb][nt][3]);
        }
    }
}

/* ============ K2: combine splits, write out cols [0,384), emit b ============ */
__global__ void combine_kernel(const float* __restrict__ x, float* __restrict__ out) {
    int row  = (blockIdx.x * blockDim.x + threadIdx.x) >> 5;
    int lane = threadIdx.x & 31;
    float2 ml[NSPLIT];
    float M = -INFINITY;
    #pragma unroll
    for (int s = 0; s < NSPLIT; ++s) {
        ml[s] = g_ml[(size_t)s * T_DIM + row];
        M = fmaxf(M, ml[s].x);
    }
    float L = 0.f, e[NSPLIT];
    #pragma unroll
    for (int s = 0; s < NSPLIT; ++s) { e[s] = __expf(ml[s].x - M); L += ml[s].y * e[s]; }
    float invL = 1.0f / L;
    float4 U = make_float4(0.f, 0.f, 0.f, 0.f);
    #pragma unroll
    for (int s = 0; s < NSPLIT; ++s) {
        float4 o = *(const float4*)&g_O[((size_t)s * T_DIM + row) * D_DIM + lane * 4];
        U.x += o.x * e[s]; U.y += o.y * e[s]; U.z += o.z * e[s]; U.w += o.w * e[s];
    }
    U.x *= invL; U.y *= invL; U.z *= invL; U.w *= invL;
    float4 c = *(const float4*)&x[(size_t)row * D_DIM + lane * 4];
    float* orow = out + (size_t)row * (4 * D_DIM);
    *(float4*)&orow[lane * 4]             = c;
    *(float4*)&orow[D_DIM + lane * 4]     = U;
    *(float4*)&orow[2 * D_DIM + lane * 4] = make_float4(c.x * U.x, c.y * U.y, c.z * U.z, c.w * U.w);
    if (lane == 0) g_b[row] = invL;   /* b = max_j A = exp(M-M)/L */
}

/* ============ K3/K4/K5: h = b @ context; out cols [384,512) = ctx*h ============ */
__global__ void hpart_kernel(const float* __restrict__ x) {
    int d = threadIdx.x;
    int r0 = blockIdx.x * 128;
    float s = 0.f;
    for (int r = 0; r < 128; ++r)
        s += g_b[r0 + r] * x[(size_t)(r0 + r) * D_DIM + d];
    g_hpart[blockIdx.x * D_DIM + d] = s;
}
__global__ void hreduce_kernel() {
    int d = threadIdx.x;
    float s = 0.f;
    #pragma unroll
    for (int b = 0; b < 64; ++b) s += g_hpart[b * D_DIM + d];
    g_h[d] = s;
}
__global__ void hwrite_kernel(const float* __restrict__ x, float* __restrict__ out) {
    int idx = blockIdx.x * blockDim.x + threadIdx.x;
    int row = idx >> 5;
    int dq  = idx & 31;
    float4 c = ((const float4*)x)[(size_t)row * 32 + dq];
    float4 h = ((const float4*)g_h)[dq];
    ((float4*)out)[(size_t)row * 128 + 96 + dq] =
        make_float4(c.x * h.x, c.y * h.y, c.z * h.z, c.w * h.w);
}

/* ============================================================================ */
extern "C" void kernel_launch(void* const* d_in, const int* in_sizes, int n_in,
                              void* d_out, int out_size) {
    const float* x    = (const float*)d_in[0];
    const float* kern = (const float*)d_in[1];
    float* out = (float*)d_out;

    cudaFuncSetAttribute(flash_kernel, cudaFuncAttributeMaxDynamicSharedMemorySize, SMEM_SZ);

    qbias_kernel<<<T_DIM / 8, 256>>>(x, kern);
    flash_kernel<<<(T_DIM / BM) * NSPLIT, NTH, SMEM_SZ>>>(x, kern);
    combine_kernel<<<(T_DIM * 32) / 256, 256>>>(x, out);
    hpart_kernel<<<64, 128>>>(x);
    hreduce_kernel<<<1, 128>>>();
    hwrite_kernel<<<(T_DIM * D_DIM / 4) / 256, 256>>>(x, out);
}

// round 4
// speedup vs baseline: 4.8661x; 1.4508x over previous
#include <cuda_runtime.h>
#include <cuda_bf16.h>
#include <math.h>
#include <stdint.h>

#define T_DIM 8192
#define D_DIM 128
#define BM 128
#define BN 64
#define NSPLIT 4
#define KEYS_PER_SPLIT (T_DIM / NSPLIT)   /* 2048 */
#define NTILES (KEYS_PER_SPLIT / BN)      /* 32   */
#define NTH 256

/* smem byte offsets: K hi/lo [64][128]bf16 swizzled, Q hi/lo [128][128]bf16 */
#define OFF_KH 0
#define OFF_KL 16384
#define OFF_QH 32768
#define OFF_QL 65536
#define OFF_QB 98304
#define SMEM_SZ 98816

__device__ float  g_qbias[T_DIM];
__device__ float  g_O[NSPLIT * T_DIM * D_DIM];
__device__ float2 g_ml[NSPLIT * T_DIM];
__device__ float  g_b[T_DIM];
__device__ float  g_hpart[256 * D_DIM];
__device__ float  g_h[D_DIM];

__device__ __forceinline__ uint32_t smem_u32(const void* p) {
    uint32_t a;
    asm("{ .reg .u64 t; cvta.to.shared.u64 t, %1; cvt.u32.u64 %0, t; }" : "=r"(a) : "l"(p));
    return a;
}

__device__ __forceinline__ void split2(float a, float b, uint32_t& hi, uint32_t& lo) {
    __nv_bfloat16 ha = __float2bfloat16(a), hb = __float2bfloat16(b);
    __nv_bfloat16 la = __float2bfloat16(a - __bfloat162float(ha));
    __nv_bfloat16 lb = __float2bfloat16(b - __bfloat162float(hb));
    __nv_bfloat162 H, L;
    H.x = ha; H.y = hb;  L.x = la; L.y = lb;
    hi = *(uint32_t*)&H;  lo = *(uint32_t*)&L;
}

#define LDSM4(r, addr) \
    asm volatile("ldmatrix.sync.aligned.m8n8.x4.shared.b16 {%0,%1,%2,%3}, [%4];" \
        : "=r"((r)[0]), "=r"((r)[1]), "=r"((r)[2]), "=r"((r)[3]) : "r"(addr))
#define LDSM4T(r, addr) \
    asm volatile("ldmatrix.sync.aligned.m8n8.x4.trans.shared.b16 {%0,%1,%2,%3}, [%4];" \
        : "=r"((r)[0]), "=r"((r)[1]), "=r"((r)[2]), "=r"((r)[3]) : "r"(addr))
#define MMA(c, a, b) \
    asm volatile("mma.sync.aligned.m16n8k16.row.col.f32.bf16.bf16.f32 " \
        "{%0,%1,%2,%3}, {%4,%5,%6,%7}, {%8,%9}, {%0,%1,%2,%3};" \
        : "+f"((c)[0]), "+f"((c)[1]), "+f"((c)[2]), "+f"((c)[3]) \
        : "r"((a)[0]), "r"((a)[1]), "r"((a)[2]), "r"((a)[3]), "r"((b)[0]), "r"((b)[1]))

/* ================= K0: qbias[j] = question[j] . w_q ================= */
__global__ void qbias_kernel(const float* __restrict__ x, const float* __restrict__ kern) {
    int j = blockIdx.x * 8 + (threadIdx.x >> 5);
    int lane = threadIdx.x & 31;
    const float* q  = x + (size_t)T_DIM * D_DIM + (size_t)j * D_DIM;
    const float* wq = kern + D_DIM;
    float s = q[lane] * wq[lane] + q[lane + 32] * wq[lane + 32]
            + q[lane + 64] * wq[lane + 64] + q[lane + 96] * wq[lane + 96];
    #pragma unroll
    for (int off = 16; off; off >>= 1) s += __shfl_xor_sync(0xffffffffu, s, off);
    if (lane == 0) g_qbias[j] = s;
}

/* ================= K1: HMMA flash, 8 warps, M16/warp ================= */
__global__ void __launch_bounds__(NTH, 2)
flash_kernel(const float* __restrict__ x, const float* __restrict__ kern)
{
    extern __shared__ char smem[];
    const uint32_t sb = smem_u32(smem);
    float* qb = (float*)(smem + OFF_QB);

    const int tid  = threadIdx.x;
    const int lane = tid & 31;
    const int w    = tid >> 5;
    const int rowblk = blockIdx.x >> 2;
    const int split  = blockIdx.x & 3;
    const int row0 = rowblk * BM;

    const float* ctx = x;
    const float* qst = x + (size_t)T_DIM * D_DIM;
    const float* wm  = kern + 2 * D_DIM;

    /* ---- prologue: Q' = ctx*w_m → bf16 hi/lo, swizzled smem ---- */
    #pragma unroll
    for (int i = 0; i < 8; ++i) {
        int idx = tid + i * NTH;
        int row = idx >> 4, ch = idx & 15;
        const float* src = ctx + (size_t)(row0 + row) * D_DIM + ch * 8;
        float4 v0 = *(const float4*)src, v1 = *(const float4*)(src + 4);
        float4 w0 = *(const float4*)&wm[ch * 8], w1 = *(const float4*)&wm[ch * 8 + 4];
        v0.x *= w0.x; v0.y *= w0.y; v0.z *= w0.z; v0.w *= w0.w;
        v1.x *= w1.x; v1.y *= w1.y; v1.z *= w1.z; v1.w *= w1.w;
        uint32_t h0, l0, h1, l1, h2, l2, h3, l3;
        split2(v0.x, v0.y, h0, l0); split2(v0.z, v0.w, h1, l1);
        split2(v1.x, v1.y, h2, l2); split2(v1.z, v1.w, h3, l3);
        uint32_t off = row * 256 + ((ch ^ (row & 7)) << 4);
        *(uint4*)(smem + OFF_QH + off) = make_uint4(h0, h1, h2, h3);
        *(uint4*)(smem + OFF_QL + off) = make_uint4(l0, l1, l2, l3);
    }

    float O[16][4];
    float m0r = -INFINITY, m1r = -INFINITY, l0r = 0.f, l1r = 0.f;
    #pragma unroll
    for (int nt = 0; nt < 16; ++nt)
        #pragma unroll
        for (int c = 0; c < 4; ++c) O[nt][c] = 0.f;

    const int m0 = w * 16;
    const int a_row  = m0 + (lane & 15);
    const int a_csel = (lane >> 4);
    const int b1_key = ((lane >> 4) << 3) + (lane & 7);
    const int b1_cs  = ((lane >> 3) & 1);
    const int b2_key = ((lane >> 3) & 1) * 8 + (lane & 7);
    const int b2_cs  = (lane >> 4);

    for (int t = 0; t < NTILES; ++t) {
        __syncthreads();
        const int kbase = split * KEYS_PER_SPLIT + t * BN;
        /* ---- load + split-convert K tile (64x128) into Kh/Kl ---- */
        #pragma unroll
        for (int i = 0; i < 4; ++i) {
            int idx = tid + i * NTH;
            int row = idx >> 4, ch = idx & 15;
            const float* src = qst + (size_t)(kbase + row) * D_DIM + ch * 8;
            float4 v0 = *(const float4*)src, v1 = *(const float4*)(src + 4);
            uint32_t h0, l0, h1, l1, h2, l2, h3, l3;
            split2(v0.x, v0.y, h0, l0); split2(v0.z, v0.w, h1, l1);
            split2(v1.x, v1.y, h2, l2); split2(v1.z, v1.w, h3, l3);
            uint32_t off = row * 256 + ((ch ^ (row & 7)) << 4);
            *(uint4*)(smem + OFF_KH + off) = make_uint4(h0, h1, h2, h3);
            *(uint4*)(smem + OFF_KL + off) = make_uint4(l0, l1, l2, l3);
        }
        if (tid < BN) qb[tid] = g_qbias[kbase + tid];
        __syncthreads();

        /* ---- GEMM1: S = Qh*Kh + Qh*Kl + Ql*Kh ---- */
        float S[8][4];
        #pragma unroll
        for (int nt = 0; nt < 8; ++nt)
            #pragma unroll
            for (int c = 0; c < 4; ++c) S[nt][c] = 0.f;

        #pragma unroll
        for (int kt = 0; kt < 8; ++kt) {
            const int ach = kt * 2 + a_csel;
            const uint32_t aoff = a_row * 256 + ((ach ^ (a_row & 7)) << 4);
            uint32_t bh[4][4], bl[4][4], aQ[4];
            #pragma unroll
            for (int np = 0; np < 4; ++np) {
                int key = np * 16 + b1_key;
                int ch  = kt * 2 + b1_cs;
                LDSM4(bh[np], sb + OFF_KH + key * 256 + ((ch ^ (key & 7)) << 4));
            }
            LDSM4(aQ, sb + OFF_QH + aoff);
            #pragma unroll
            for (int np = 0; np < 4; ++np) {
                MMA(S[2 * np],     aQ, &bh[np][0]);
                MMA(S[2 * np + 1], aQ, &bh[np][2]);
            }
            #pragma unroll
            for (int np = 0; np < 4; ++np) {
                int key = np * 16 + b1_key;
                int ch  = kt * 2 + b1_cs;
                LDSM4(bl[np], sb + OFF_KL + key * 256 + ((ch ^ (key & 7)) << 4));
            }
            #pragma unroll
            for (int np = 0; np < 4; ++np) {
                MMA(S[2 * np],     aQ, &bl[np][0]);
                MMA(S[2 * np + 1], aQ, &bl[np][2]);
            }
            LDSM4(aQ, sb + OFF_QL + aoff);   /* Ql */
            #pragma unroll
            for (int np = 0; np < 4; ++np) {
                MMA(S[2 * np],     aQ, &bh[np][0]);
                MMA(S[2 * np + 1], aQ, &bh[np][2]);
            }
        }

        /* ---- online softmax ---- */
        float qv[16];
        #pragma unroll
        for (int i = 0; i < 8; ++i) {
            float2 tq = *(const float2*)&qb[i * 8 + (lane & 3) * 2];
            qv[2 * i] = tq.x; qv[2 * i + 1] = tq.y;
        }
        uint32_t P[8][2];
        {
            float mx0 = -INFINITY, mx1 = -INFINITY;
            #pragma unroll
            for (int nt = 0; nt < 8; ++nt) {
                S[nt][0] += qv[2 * nt]; S[nt][1] += qv[2 * nt + 1];
                S[nt][2] += qv[2 * nt]; S[nt][3] += qv[2 * nt + 1];
                mx0 = fmaxf(mx0, fmaxf(S[nt][0], S[nt][1]));
                mx1 = fmaxf(mx1, fmaxf(S[nt][2], S[nt][3]));
            }
            mx0 = fmaxf(mx0, __shfl_xor_sync(0xffffffffu, mx0, 1));
            mx0 = fmaxf(mx0, __shfl_xor_sync(0xffffffffu, mx0, 2));
            mx1 = fmaxf(mx1, __shfl_xor_sync(0xffffffffu, mx1, 1));
            mx1 = fmaxf(mx1, __shfl_xor_sync(0xffffffffu, mx1, 2));
            float mn0 = fmaxf(m0r, mx0), mn1 = fmaxf(m1r, mx1);
            float al0 = __expf(m0r - mn0), al1 = __expf(m1r - mn1);
            m0r = mn0; m1r = mn1;
            float ls0 = 0.f, ls1 = 0.f;
            #pragma unroll
            for (int nt = 0; nt < 8; ++nt) {
                float p0 = __expf(S[nt][0] - mn0);
                float p1 = __expf(S[nt][1] - mn0);
                float p2 = __expf(S[nt][2] - mn1);
                float p3 = __expf(S[nt][3] - mn1);
                __nv_bfloat162 b01, b23;
                b01.x = __float2bfloat16(p0); b01.y = __float2bfloat16(p1);
                b23.x = __float2bfloat16(p2); b23.y = __float2bfloat16(p3);
                ls0 += __bfloat162float(b01.x) + __bfloat162float(b01.y);
                ls1 += __bfloat162float(b23.x) + __bfloat162float(b23.y);
                P[nt][0] = *(uint32_t*)&b01;
                P[nt][1] = *(uint32_t*)&b23;
            }
            ls0 += __shfl_xor_sync(0xffffffffu, ls0, 1);
            ls0 += __shfl_xor_sync(0xffffffffu, ls0, 2);
            ls1 += __shfl_xor_sync(0xffffffffu, ls1, 1);
            ls1 += __shfl_xor_sync(0xffffffffu, ls1, 2);
            l0r = l0r * al0 + ls0;
            l1r = l1r * al1 + ls1;
            #pragma unroll
            for (int nt = 0; nt < 16; ++nt) {
                O[nt][0] *= al0; O[nt][1] *= al0;
                O[nt][2] *= al1; O[nt][3] *= al1;
            }
        }

        /* ---- GEMM2: O += P*Vh + P*Vl ---- */
        #pragma unroll
        for (int kt2 = 0; kt2 < 4; ++kt2) {
            uint32_t aP[4] = { P[2 * kt2][0], P[2 * kt2][1],
                               P[2 * kt2 + 1][0], P[2 * kt2 + 1][1] };
            const int key = kt2 * 16 + b2_key;
            const uint32_t krow = key * 256 + sb;
            #pragma unroll
            for (int dp = 0; dp < 8; ++dp) {
                uint32_t bv[4];
                int ch = dp * 2 + b2_cs;
                LDSM4T(bv, krow + OFF_KH + ((ch ^ (key & 7)) << 4));
                MMA(O[2 * dp],     aP, &bv[0]);
                MMA(O[2 * dp + 1], aP, &bv[2]);
            }
            #pragma unroll
            for (int dp = 0; dp < 8; ++dp) {
                uint32_t bv[4];
                int ch = dp * 2 + b2_cs;
                LDSM4T(bv, krow + OFF_KL + ((ch ^ (key & 7)) << 4));
                MMA(O[2 * dp],     aP, &bv[0]);
                MMA(O[2 * dp + 1], aP, &bv[2]);
            }
        }
    }

    /* ---- epilogue ---- */
    {
        int r1 = row0 + m0 + (lane >> 2);
        int r2 = r1 + 8;
        if ((lane & 3) == 0) {
            g_ml[(size_t)split * T_DIM + r1] = make_float2(m0r, l0r);
            g_ml[(size_t)split * T_DIM + r2] = make_float2(m1r, l1r);
        }
        float* o1 = g_O + ((size_t)split * T_DIM + r1) * D_DIM + (lane & 3) * 2;
        float* o2 = g_O + ((size_t)split * T_DIM + r2) * D_DIM + (lane & 3) * 2;
        #pragma unroll
        for (int nt = 0; nt < 16; ++nt) {
            *(float2*)(o1 + nt * 8) = make_float2(O[nt][0], O[nt][1]);
            *(float2*)(o2 + nt * 8) = make_float2(O[nt][2], O[nt][3]);
        }
    }
}

/* ============ K2: combine splits, write out cols [0,384), emit b ============ */
__global__ void combine_kernel(const float* __restrict__ x, float* __restrict__ out) {
    int row  = (blockIdx.x * blockDim.x + threadIdx.x) >> 5;
    int lane = threadIdx.x & 31;
    float2 ml[NSPLIT];
    float M = -INFINITY;
    #pragma unroll
    for (int s = 0; s < NSPLIT; ++s) {
        ml[s] = g_ml[(size_t)s * T_DIM + row];
        M = fmaxf(M, ml[s].x);
    }
    float L = 0.f, e[NSPLIT];
    #pragma unroll
    for (int s = 0; s < NSPLIT; ++s) { e[s] = __expf(ml[s].x - M); L += ml[s].y * e[s]; }
    float invL = 1.0f / L;
    float4 U = make_float4(0.f, 0.f, 0.f, 0.f);
    #pragma unroll
    for (int s = 0; s < NSPLIT; ++s) {
        float4 o = *(const float4*)&g_O[((size_t)s * T_DIM + row) * D_DIM + lane * 4];
        U.x += o.x * e[s]; U.y += o.y * e[s]; U.z += o.z * e[s]; U.w += o.w * e[s];
    }
    U.x *= invL; U.y *= invL; U.z *= invL; U.w *= invL;
    float4 c = *(const float4*)&x[(size_t)row * D_DIM + lane * 4];
    float* orow = out + (size_t)row * (4 * D_DIM);
    *(float4*)&orow[lane * 4]             = c;
    *(float4*)&orow[D_DIM + lane * 4]     = U;
    *(float4*)&orow[2 * D_DIM + lane * 4] = make_float4(c.x * U.x, c.y * U.y, c.z * U.z, c.w * U.w);
    if (lane == 0) g_b[row] = invL;
}

/* ============ K3/K4/K5: h = b @ context; out cols [384,512) = ctx*h ============ */
__global__ void hpart_kernel(const float* __restrict__ x) {
    int d = threadIdx.x;
    int r0 = blockIdx.x * 32;
    float s = 0.f;
    #pragma unroll 8
    for (int r = 0; r < 32; ++r)
        s += g_b[r0 + r] * x[(size_t)(r0 + r) * D_DIM + d];
    g_hpart[blockIdx.x * D_DIM + d] = s;
}
__global__ void hreduce_kernel() {
    int d = threadIdx.x;
    float s = 0.f;
    #pragma unroll 16
    for (int b = 0; b < 256; ++b) s += g_hpart[b * D_DIM + d];
    g_h[d] = s;
}
__global__ void hwrite_kernel(const float* __restrict__ x, float* __restrict__ out) {
    int idx = blockIdx.x * blockDim.x + threadIdx.x;
    int row = idx >> 5;
    int dq  = idx & 31;
    float4 c = ((const float4*)x)[(size_t)row * 32 + dq];
    float4 h = ((const float4*)g_h)[dq];
    ((float4*)out)[(size_t)row * 128 + 96 + dq] =
        make_float4(c.x * h.x, c.y * h.y, c.z * h.z, c.w * h.w);
}

/* ============================================================================ */
extern "C" void kernel_launch(void* const* d_in, const int* in_sizes, int n_in,
                              void* d_out, int out_size) {
    const float* x    = (const float*)d_in[0];
    const float* kern = (const float*)d_in[1];
    float* out = (float*)d_out;

    cudaFuncSetAttribute(flash_kernel, cudaFuncAttributeMaxDynamicSharedMemorySize, SMEM_SZ);

    qbias_kernel<<<T_DIM / 8, 256>>>(x, kern);
    flash_kernel<<<(T_DIM / BM) * NSPLIT, NTH, SMEM_SZ>>>(x, kern);
    combine_kernel<<<(T_DIM * 32) / 256, 256>>>(x, out);
    hpart_kernel<<<256, 128>>>(x);
    hreduce_kernel<<<1, 128>>>();
    hwrite_kernel<<<(T_DIM * D_DIM / 4) / 256, 256>>>(x, out);
}

// round 5
// speedup vs baseline: 6.0513x; 1.2436x over previous
#include <cuda_runtime.h>
#include <cuda_bf16.h>
#include <math.h>
#include <stdint.h>

#define T_DIM 8192
#define D_DIM 128
#define BM 128
#define BN 64
#define NSPLIT 2
#define KEYS_PER_SPLIT (T_DIM / NSPLIT)   /* 4096 */
#define NTILES (KEYS_PER_SPLIT / BN)      /* 64   */
#define NTH 256

/* smem: two K buffers (KH 16K + KL 16K each) + qbias double buffer */
#define BUF_STRIDE 32768
#define OFF_KH 0
#define OFF_KL 16384
#define OFF_QB 65536
#define SMEM_SZ 66048

__device__ float  g_qbias[T_DIM];
__device__ float  g_O[NSPLIT * T_DIM * D_DIM];
__device__ float2 g_ml[NSPLIT * T_DIM];
__device__ float  g_b[T_DIM];
__device__ float  g_hpart[256 * D_DIM];
__device__ float  g_h[D_DIM];

__device__ __forceinline__ uint32_t smem_u32(const void* p) {
    uint32_t a;
    asm("{ .reg .u64 t; cvta.to.shared.u64 t, %1; cvt.u32.u64 %0, t; }" : "=r"(a) : "l"(p));
    return a;
}

__device__ __forceinline__ void split2(float a, float b, uint32_t& hi, uint32_t& lo) {
    __nv_bfloat16 ha = __float2bfloat16(a), hb = __float2bfloat16(b);
    __nv_bfloat16 la = __float2bfloat16(a - __bfloat162float(ha));
    __nv_bfloat16 lb = __float2bfloat16(b - __bfloat162float(hb));
    __nv_bfloat162 H, L;
    H.x = ha; H.y = hb;  L.x = la; L.y = lb;
    hi = *(uint32_t*)&H;  lo = *(uint32_t*)&L;
}

#define LDSM4(r, addr) \
    asm volatile("ldmatrix.sync.aligned.m8n8.x4.shared.b16 {%0,%1,%2,%3}, [%4];" \
        : "=r"((r)[0]), "=r"((r)[1]), "=r"((r)[2]), "=r"((r)[3]) : "r"(addr))
#define LDSM4T(r, addr) \
    asm volatile("ldmatrix.sync.aligned.m8n8.x4.trans.shared.b16 {%0,%1,%2,%3}, [%4];" \
        : "=r"((r)[0]), "=r"((r)[1]), "=r"((r)[2]), "=r"((r)[3]) : "r"(addr))
#define MMA(c, a, b) \
    asm volatile("mma.sync.aligned.m16n8k16.row.col.f32.bf16.bf16.f32 " \
        "{%0,%1,%2,%3}, {%4,%5,%6,%7}, {%8,%9}, {%0,%1,%2,%3};" \
        : "+f"((c)[0]), "+f"((c)[1]), "+f"((c)[2]), "+f"((c)[3]) \
        : "r"((a)[0]), "r"((a)[1]), "r"((a)[2]), "r"((a)[3]), "r"((b)[0]), "r"((b)[1]))

/* ================= K0: qbias[j] = question[j] . w_q ================= */
__global__ void qbias_kernel(const float* __restrict__ x, const float* __restrict__ kern) {
    int j = blockIdx.x * 8 + (threadIdx.x >> 5);
    int lane = threadIdx.x & 31;
    const float* q  = x + (size_t)T_DIM * D_DIM + (size_t)j * D_DIM;
    const float* wq = kern + D_DIM;
    float s = q[lane] * wq[lane] + q[lane + 32] * wq[lane + 32]
            + q[lane + 64] * wq[lane + 64] + q[lane + 96] * wq[lane + 96];
    #pragma unroll
    for (int off = 16; off; off >>= 1) s += __shfl_xor_sync(0xffffffffu, s, off);
    if (lane == 0) g_qbias[j] = s;
}

/* ================= K1: HMMA flash, Q-frags in regs, double-buffered K ================= */
__global__ void __launch_bounds__(NTH, 1)
flash_kernel(const float* __restrict__ x, const float* __restrict__ kern)
{
    extern __shared__ char smem[];
    const uint32_t sb = smem_u32(smem);

    const int tid  = threadIdx.x;
    const int lane = tid & 31;
    const int w    = tid >> 5;
    const int rowblk = blockIdx.x >> 1;
    const int split  = blockIdx.x & 1;
    const int row0 = rowblk * BM;

    const float* ctx = x;
    const float* qst = x + (size_t)T_DIM * D_DIM;
    const float* wm  = kern + 2 * D_DIM;

    /* ---- prologue A: Q' = ctx*w_m → bf16 hi/lo staged in smem (hi@0, lo@32768) ---- */
    #pragma unroll
    for (int i = 0; i < 8; ++i) {
        int idx = tid + i * NTH;
        int row = idx >> 4, ch = idx & 15;
        const float* src = ctx + (size_t)(row0 + row) * D_DIM + ch * 8;
        float4 v0 = *(const float4*)src, v1 = *(const float4*)(src + 4);
        float4 w0 = *(const float4*)&wm[ch * 8], w1 = *(const float4*)&wm[ch * 8 + 4];
        v0.x *= w0.x; v0.y *= w0.y; v0.z *= w0.z; v0.w *= w0.w;
        v1.x *= w1.x; v1.y *= w1.y; v1.z *= w1.z; v1.w *= w1.w;
        uint32_t h0, l0, h1, l1, h2, l2, h3, l3;
        split2(v0.x, v0.y, h0, l0); split2(v0.z, v0.w, h1, l1);
        split2(v1.x, v1.y, h2, l2); split2(v1.z, v1.w, h3, l3);
        uint32_t off = row * 256 + ((ch ^ (row & 7)) << 4);
        *(uint4*)(smem + off)         = make_uint4(h0, h1, h2, h3);
        *(uint4*)(smem + 32768 + off) = make_uint4(l0, l1, l2, l3);
    }
    __syncthreads();

    /* ---- prologue B: load loop-invariant Q A-fragments into registers ---- */
    const int m0 = w * 16;
    const int a_row = m0 + (lane & 15);
    const int a_cs  = (lane >> 4);
    uint32_t aQh[8][4], aQl[8][4];
    #pragma unroll
    for (int kt = 0; kt < 8; ++kt) {
        int ach = kt * 2 + a_cs;
        uint32_t aoff = a_row * 256 + ((ach ^ (a_row & 7)) << 4);
        LDSM4(aQh[kt], sb + aoff);
        LDSM4(aQl[kt], sb + 32768 + aoff);
    }
    __syncthreads();   /* Q staging reads done — buffers now free for K */

    /* ---- prologue C: K tile 0 → buf0 ---- */
    const int srow = tid >> 4, sch = tid & 15;
    {
        const int kbase = split * KEYS_PER_SPLIT;
        #pragma unroll
        for (int i = 0; i < 4; ++i) {
            int row = srow + 16 * i;
            const float* src = qst + (size_t)(kbase + row) * D_DIM + sch * 8;
            float4 v0 = *(const float4*)src, v1 = *(const float4*)(src + 4);
            uint32_t h0, l0, h1, l1, h2, l2, h3, l3;
            split2(v0.x, v0.y, h0, l0); split2(v0.z, v0.w, h1, l1);
            split2(v1.x, v1.y, h2, l2); split2(v1.z, v1.w, h3, l3);
            uint32_t off = row * 256 + ((sch ^ (row & 7)) << 4);
            *(uint4*)(smem + OFF_KH + off) = make_uint4(h0, h1, h2, h3);
            *(uint4*)(smem + OFF_KL + off) = make_uint4(l0, l1, l2, l3);
        }
        if (tid < BN) ((float*)(smem + OFF_QB))[tid] = g_qbias[kbase + tid];
    }

    float O[16][4];
    float m0r = -INFINITY, m1r = -INFINITY, l0r = 0.f, l1r = 0.f;
    #pragma unroll
    for (int nt = 0; nt < 16; ++nt)
        #pragma unroll
        for (int c = 0; c < 4; ++c) O[nt][c] = 0.f;

    const int b1_key = ((lane >> 4) << 3) + (lane & 7);
    const int b1_cs  = ((lane >> 3) & 1);
    const int b2_key = ((lane >> 3) & 1) * 8 + (lane & 7);
    const int b2_cs  = (lane >> 4);

    for (int t = 0; t < NTILES; ++t) {
        __syncthreads();   /* buf[t&1] ready; buf[(t+1)&1] free */
        const uint32_t bufR = (uint32_t)(t & 1) * BUF_STRIDE;
        const uint32_t bufW = (uint32_t)((t + 1) & 1) * BUF_STRIDE;
        const bool has_next = (t + 1 < NTILES);

        /* ---- stage fp32 loads of K tile t+1 (latency hidden under GEMM1) ---- */
        float4 sA[4], sB[4];
        float sqb = 0.f;
        if (has_next) {
            const int kb = split * KEYS_PER_SPLIT + (t + 1) * BN;
            #pragma unroll
            for (int i = 0; i < 4; ++i) {
                const float* src = qst + (size_t)(kb + srow + 16 * i) * D_DIM + sch * 8;
                sA[i] = *(const float4*)src;
                sB[i] = *(const float4*)(src + 4);
            }
            if (tid < BN) sqb = g_qbias[kb + tid];
        }

        /* ---- GEMM1: S = Qh*Kh + Ql*Kh + Qh*Kl ---- */
        float S[8][4];
        #pragma unroll
        for (int nt = 0; nt < 8; ++nt)
            #pragma unroll
            for (int c = 0; c < 4; ++c) S[nt][c] = 0.f;

        #pragma unroll
        for (int kt = 0; kt < 8; ++kt) {
            uint32_t bh[4][4];
            #pragma unroll
            for (int np = 0; np < 4; ++np) {
                int key = np * 16 + b1_key;
                int ch  = kt * 2 + b1_cs;
                LDSM4(bh[np], sb + bufR + OFF_KH + key * 256 + ((ch ^ (key & 7)) << 4));
            }
            #pragma unroll
            for (int np = 0; np < 4; ++np) {
                MMA(S[2 * np],     aQh[kt], &bh[np][0]);
                MMA(S[2 * np + 1], aQh[kt], &bh[np][2]);
            }
            #pragma unroll
            for (int np = 0; np < 4; ++np) {
                MMA(S[2 * np],     aQl[kt], &bh[np][0]);
                MMA(S[2 * np + 1], aQl[kt], &bh[np][2]);
            }
            #pragma unroll
            for (int np = 0; np < 4; ++np) {   /* reuse regs for Kl */
                int key = np * 16 + b1_key;
                int ch  = kt * 2 + b1_cs;
                LDSM4(bh[np], sb + bufR + OFF_KL + key * 256 + ((ch ^ (key & 7)) << 4));
            }
            #pragma unroll
            for (int np = 0; np < 4; ++np) {
                MMA(S[2 * np],     aQh[kt], &bh[np][0]);
                MMA(S[2 * np + 1], aQh[kt], &bh[np][2]);
            }
        }

        /* ---- convert + store staged tile t+1 into the free buffer ---- */
        if (has_next) {
            #pragma unroll
            for (int i = 0; i < 4; ++i) {
                int row = srow + 16 * i;
                uint32_t h0, l0, h1, l1, h2, l2, h3, l3;
                split2(sA[i].x, sA[i].y, h0, l0); split2(sA[i].z, sA[i].w, h1, l1);
                split2(sB[i].x, sB[i].y, h2, l2); split2(sB[i].z, sB[i].w, h3, l3);
                uint32_t off = row * 256 + ((sch ^ (row & 7)) << 4);
                *(uint4*)(smem + bufW + OFF_KH + off) = make_uint4(h0, h1, h2, h3);
                *(uint4*)(smem + bufW + OFF_KL + off) = make_uint4(l0, l1, l2, l3);
            }
            if (tid < BN) ((float*)(smem + OFF_QB + ((t + 1) & 1) * 256))[tid] = sqb;
        }

        /* ---- online softmax ---- */
        const float* qbp = (const float*)(smem + OFF_QB + (t & 1) * 256);
        uint32_t P[8][2];
        {
            float mx0 = -INFINITY, mx1 = -INFINITY;
            #pragma unroll
            for (int nt = 0; nt < 8; ++nt) {
                float2 tq = *(const float2*)&qbp[nt * 8 + (lane & 3) * 2];
                S[nt][0] += tq.x; S[nt][1] += tq.y;
                S[nt][2] += tq.x; S[nt][3] += tq.y;
                mx0 = fmaxf(mx0, fmaxf(S[nt][0], S[nt][1]));
                mx1 = fmaxf(mx1, fmaxf(S[nt][2], S[nt][3]));
            }
            mx0 = fmaxf(mx0, __shfl_xor_sync(0xffffffffu, mx0, 1));
            mx0 = fmaxf(mx0, __shfl_xor_sync(0xffffffffu, mx0, 2));
            mx1 = fmaxf(mx1, __shfl_xor_sync(0xffffffffu, mx1, 1));
            mx1 = fmaxf(mx1, __shfl_xor_sync(0xffffffffu, mx1, 2));
            float mn0 = fmaxf(m0r, mx0), mn1 = fmaxf(m1r, mx1);
            float al0 = __expf(m0r - mn0), al1 = __expf(m1r - mn1);
            m0r = mn0; m1r = mn1;
            float ls0 = 0.f, ls1 = 0.f;
            #pragma unroll
            for (int nt = 0; nt < 8; ++nt) {
                float p0 = __expf(S[nt][0] - mn0);
                float p1 = __expf(S[nt][1] - mn0);
                float p2 = __expf(S[nt][2] - mn1);
                float p3 = __expf(S[nt][3] - mn1);
                __nv_bfloat162 b01, b23;
                b01.x = __float2bfloat16(p0); b01.y = __float2bfloat16(p1);
                b23.x = __float2bfloat16(p2); b23.y = __float2bfloat16(p3);
                /* l from ROUNDED P for O/l consistency */
                ls0 += __bfloat162float(b01.x) + __bfloat162float(b01.y);
                ls1 += __bfloat162float(b23.x) + __bfloat162float(b23.y);
                P[nt][0] = *(uint32_t*)&b01;
                P[nt][1] = *(uint32_t*)&b23;
            }
            ls0 += __shfl_xor_sync(0xffffffffu, ls0, 1);
            ls0 += __shfl_xor_sync(0xffffffffu, ls0, 2);
            ls1 += __shfl_xor_sync(0xffffffffu, ls1, 1);
            ls1 += __shfl_xor_sync(0xffffffffu, ls1, 2);
            l0r = l0r * al0 + ls0;
            l1r = l1r * al1 + ls1;
            #pragma unroll
            for (int nt = 0; nt < 16; ++nt) {
                O[nt][0] *= al0; O[nt][1] *= al0;
                O[nt][2] *= al1; O[nt][3] *= al1;
            }
        }

        /* ---- GEMM2: O += P * Vh  (single bf16 V; B via ldmatrix.trans of KH) ---- */
        #pragma unroll
        for (int kt2 = 0; kt2 < 4; ++kt2) {
            uint32_t aP[4] = { P[2 * kt2][0], P[2 * kt2][1],
                               P[2 * kt2 + 1][0], P[2 * kt2 + 1][1] };
            const int key = kt2 * 16 + b2_key;
            const uint32_t krow = sb + bufR + OFF_KH + key * 256;
            #pragma unroll
            for (int dp = 0; dp < 8; ++dp) {
                uint32_t bv[4];
                int ch = dp * 2 + b2_cs;
                LDSM4T(bv, krow + ((ch ^ (key & 7)) << 4));
                MMA(O[2 * dp],     aP, &bv[0]);
                MMA(O[2 * dp + 1], aP, &bv[2]);
            }
        }
    }

    /* ---- epilogue ---- */
    {
        int r1 = row0 + m0 + (lane >> 2);
        int r2 = r1 + 8;
        if ((lane & 3) == 0) {
            g_ml[(size_t)split * T_DIM + r1] = make_float2(m0r, l0r);
            g_ml[(size_t)split * T_DIM + r2] = make_float2(m1r, l1r);
        }
        float* o1 = g_O + ((size_t)split * T_DIM + r1) * D_DIM + (lane & 3) * 2;
        float* o2 = g_O + ((size_t)split * T_DIM + r2) * D_DIM + (lane & 3) * 2;
        #pragma unroll
        for (int nt = 0; nt < 16; ++nt) {
            *(float2*)(o1 + nt * 8) = make_float2(O[nt][0], O[nt][1]);
            *(float2*)(o2 + nt * 8) = make_float2(O[nt][2], O[nt][3]);
        }
    }
}

/* ============ K2: combine splits, write out cols [0,384), emit b ============ */
__global__ void combine_kernel(const float* __restrict__ x, float* __restrict__ out) {
    int row  = (blockIdx.x * blockDim.x + threadIdx.x) >> 5;
    int lane = threadIdx.x & 31;
    float2 ml[NSPLIT];
    float M = -INFINITY;
    #pragma unroll
    for (int s = 0; s < NSPLIT; ++s) {
        ml[s] = g_ml[(size_t)s * T_DIM + row];
        M = fmaxf(M, ml[s].x);
    }
    float L = 0.f, e[NSPLIT];
    #pragma unroll
    for (int s = 0; s < NSPLIT; ++s) { e[s] = __expf(ml[s].x - M); L += ml[s].y * e[s]; }
    float invL = 1.0f / L;
    float4 U = make_float4(0.f, 0.f, 0.f, 0.f);
    #pragma unroll
    for (int s = 0; s < NSPLIT; ++s) {
        float4 o = *(const float4*)&g_O[((size_t)s * T_DIM + row) * D_DIM + lane * 4];
        U.x += o.x * e[s]; U.y += o.y * e[s]; U.z += o.z * e[s]; U.w += o.w * e[s];
    }
    U.x *= invL; U.y *= invL; U.z *= invL; U.w *= invL;
    float4 c = *(const float4*)&x[(size_t)row * D_DIM + lane * 4];
    float* orow = out + (size_t)row * (4 * D_DIM);
    *(float4*)&orow[lane * 4]             = c;
    *(float4*)&orow[D_DIM + lane * 4]     = U;
    *(float4*)&orow[2 * D_DIM + lane * 4] = make_float4(c.x * U.x, c.y * U.y, c.z * U.z, c.w * U.w);
    if (lane == 0) g_b[row] = invL;
}

/* ============ K3/K4/K5: h = b @ context; out cols [384,512) = ctx*h ============ */
__global__ void hpart_kernel(const float* __restrict__ x) {
    int d = threadIdx.x;
    int r0 = blockIdx.x * 32;
    float s = 0.f;
    #pragma unroll 8
    for (int r = 0; r < 32; ++r)
        s += g_b[r0 + r] * x[(size_t)(r0 + r) * D_DIM + d];
    g_hpart[blockIdx.x * D_DIM + d] = s;
}
__global__ void hreduce_kernel() {
    int d = threadIdx.x;
    float s = 0.f;
    #pragma unroll 16
    for (int b = 0; b < 256; ++b) s += g_hpart[b * D_DIM + d];
    g_h[d] = s;
}
__global__ void hwrite_kernel(const float* __restrict__ x, float* __restrict__ out) {
    int idx = blockIdx.x * blockDim.x + threadIdx.x;
    int row = idx >> 5;
    int dq  = idx & 31;
    float4 c = ((const float4*)x)[(size_t)row * 32 + dq];
    float4 h = ((const float4*)g_h)[dq];
    ((float4*)out)[(size_t)row * 128 + 96 + dq] =
        make_float4(c.x * h.x, c.y * h.y, c.z * h.z, c.w * h.w);
}

/* ============================================================================ */
extern "C" void kernel_launch(void* const* d_in, const int* in_sizes, int n_in,
                              void* d_out, int out_size) {
    const float* x    = (const float*)d_in[0];
    const float* kern = (const float*)d_in[1];
    float* out = (float*)d_out;

    cudaFuncSetAttribute(flash_kernel, cudaFuncAttributeMaxDynamicSharedMemorySize, SMEM_SZ);

    qbias_kernel<<<T_DIM / 8, 256>>>(x, kern);
    flash_kernel<<<(T_DIM / BM) * NSPLIT, NTH, SMEM_SZ>>>(x, kern);
    combine_kernel<<<(T_DIM * 32) / 256, 256>>>(x, out);
    hpart_kernel<<<256, 128>>>(x);
    hreduce_kernel<<<1, 128>>>();
    hwrite_kernel<<<(T_DIM * D_DIM / 4) / 256, 256>>>(x, out);
}

// round 6
// speedup vs baseline: 6.4484x; 1.0656x over previous
#include <cuda_runtime.h>
#include <cuda_bf16.h>
#include <math.h>
#include <stdint.h>

#define T_DIM 8192
#define D_DIM 128
#define BM 128
#define BN 64
#define NSPLIT 2
#define KEYS_PER_SPLIT (T_DIM / NSPLIT)   /* 4096 */
#define NTILES (KEYS_PER_SPLIT / BN)      /* 64   */
#define NTH 256
#define LOG2E 1.4426950408889634f

/* smem: two K buffers (KH 16K + KL 16K each) + qbias double buffer */
#define BUF_STRIDE 32768
#define OFF_KH 0
#define OFF_KL 16384
#define OFF_QB 65536
#define SMEM_SZ 66048

__device__ float  g_qbias[T_DIM];
__device__ float  g_O[NSPLIT * T_DIM * D_DIM];
__device__ float4 g_ml[NSPLIT * T_DIM];   /* (m_scale, p_max, l, 0) base-2 domain */
__device__ float  g_b[T_DIM];
__device__ float  g_hpart[256 * D_DIM];
__device__ float  g_h[D_DIM];

__device__ __forceinline__ uint32_t smem_u32(const void* p) {
    uint32_t a;
    asm("{ .reg .u64 t; cvta.to.shared.u64 t, %1; cvt.u32.u64 %0, t; }" : "=r"(a) : "l"(p));
    return a;
}
__device__ __forceinline__ float ex2(float x) {
    float y;
    asm("ex2.approx.f32 %0, %1;" : "=f"(y) : "f"(x));
    return y;
}

__device__ __forceinline__ void split2(float a, float b, uint32_t& hi, uint32_t& lo) {
    __nv_bfloat16 ha = __float2bfloat16(a), hb = __float2bfloat16(b);
    __nv_bfloat16 la = __float2bfloat16(a - __bfloat162float(ha));
    __nv_bfloat16 lb = __float2bfloat16(b - __bfloat162float(hb));
    __nv_bfloat162 H, L;
    H.x = ha; H.y = hb;  L.x = la; L.y = lb;
    hi = *(uint32_t*)&H;  lo = *(uint32_t*)&L;
}

#define LDSM4(r, addr) \
    asm volatile("ldmatrix.sync.aligned.m8n8.x4.shared.b16 {%0,%1,%2,%3}, [%4];" \
        : "=r"((r)[0]), "=r"((r)[1]), "=r"((r)[2]), "=r"((r)[3]) : "r"(addr))
#define LDSM4T(r, addr) \
    asm volatile("ldmatrix.sync.aligned.m8n8.x4.trans.shared.b16 {%0,%1,%2,%3}, [%4];" \
        : "=r"((r)[0]), "=r"((r)[1]), "=r"((r)[2]), "=r"((r)[3]) : "r"(addr))
#define MMA(c, a, b) \
    asm volatile("mma.sync.aligned.m16n8k16.row.col.f32.bf16.bf16.f32 " \
        "{%0,%1,%2,%3}, {%4,%5,%6,%7}, {%8,%9}, {%0,%1,%2,%3};" \
        : "+f"((c)[0]), "+f"((c)[1]), "+f"((c)[2]), "+f"((c)[3]) \
        : "r"((a)[0]), "r"((a)[1]), "r"((a)[2]), "r"((a)[3]), "r"((b)[0]), "r"((b)[1]))

/* ================= K0: qbias[j] = (question[j] . w_q) * log2(e) ================= */
__global__ void qbias_kernel(const float* __restrict__ x, const float* __restrict__ kern) {
    int j = blockIdx.x * 8 + (threadIdx.x >> 5);
    int lane = threadIdx.x & 31;
    const float* q  = x + (size_t)T_DIM * D_DIM + (size_t)j * D_DIM;
    const float* wq = kern + D_DIM;
    float s = q[lane] * wq[lane] + q[lane + 32] * wq[lane + 32]
            + q[lane + 64] * wq[lane + 64] + q[lane + 96] * wq[lane + 96];
    #pragma unroll
    for (int off = 16; off; off >>= 1) s += __shfl_xor_sync(0xffffffffu, s, off);
    if (lane == 0) g_qbias[j] = s * LOG2E;
}

/* ================= K1: HMMA flash, static-scale base-2 softmax ================= */
__global__ void __launch_bounds__(NTH, 1)
flash_kernel(const float* __restrict__ x, const float* __restrict__ kern)
{
    extern __shared__ char smem[];
    const uint32_t sb = smem_u32(smem);

    const int tid  = threadIdx.x;
    const int lane = tid & 31;
    const int w    = tid >> 5;
    const int rowblk = blockIdx.x >> 1;
    const int split  = blockIdx.x & 1;
    const int row0 = rowblk * BM;

    const float* ctx = x;
    const float* qst = x + (size_t)T_DIM * D_DIM;
    const float* wm  = kern + 2 * D_DIM;

    /* ---- prologue A: Q' = ctx*w_m*log2e → bf16 hi/lo staged in smem ---- */
    #pragma unroll
    for (int i = 0; i < 8; ++i) {
        int idx = tid + i * NTH;
        int row = idx >> 4, ch = idx & 15;
        const float* src = ctx + (size_t)(row0 + row) * D_DIM + ch * 8;
        float4 v0 = *(const float4*)src, v1 = *(const float4*)(src + 4);
        float4 w0 = *(const float4*)&wm[ch * 8], w1 = *(const float4*)&wm[ch * 8 + 4];
        w0.x *= LOG2E; w0.y *= LOG2E; w0.z *= LOG2E; w0.w *= LOG2E;
        w1.x *= LOG2E; w1.y *= LOG2E; w1.z *= LOG2E; w1.w *= LOG2E;
        v0.x *= w0.x; v0.y *= w0.y; v0.z *= w0.z; v0.w *= w0.w;
        v1.x *= w1.x; v1.y *= w1.y; v1.z *= w1.z; v1.w *= w1.w;
        uint32_t h0, l0, h1, l1, h2, l2, h3, l3;
        split2(v0.x, v0.y, h0, l0); split2(v0.z, v0.w, h1, l1);
        split2(v1.x, v1.y, h2, l2); split2(v1.z, v1.w, h3, l3);
        uint32_t off = row * 256 + ((ch ^ (row & 7)) << 4);
        *(uint4*)(smem + off)         = make_uint4(h0, h1, h2, h3);
        *(uint4*)(smem + 32768 + off) = make_uint4(l0, l1, l2, l3);
    }
    __syncthreads();

    /* ---- prologue B: loop-invariant Q A-fragments into registers ---- */
    const int m0 = w * 16;
    const int a_row = m0 + (lane & 15);
    const int a_cs  = (lane >> 4);
    uint32_t aQh[8][4], aQl[8][4];
    #pragma unroll
    for (int kt = 0; kt < 8; ++kt) {
        int ach = kt * 2 + a_cs;
        uint32_t aoff = a_row * 256 + ((ach ^ (a_row & 7)) << 4);
        LDSM4(aQh[kt], sb + aoff);
        LDSM4(aQl[kt], sb + 32768 + aoff);
    }
    __syncthreads();   /* Q staging reads done — buffers now free for K */

    /* ---- prologue C: K tile 0 → buf0 ---- */
    const int srow = tid >> 4, sch = tid & 15;
    {
        const int kbase = split * KEYS_PER_SPLIT;
        #pragma unroll
        for (int i = 0; i < 4; ++i) {
            int row = srow + 16 * i;
            const float* src = qst + (size_t)(kbase + row) * D_DIM + sch * 8;
            float4 v0 = *(const float4*)src, v1 = *(const float4*)(src + 4);
            uint32_t h0, l0, h1, l1, h2, l2, h3, l3;
            split2(v0.x, v0.y, h0, l0); split2(v0.z, v0.w, h1, l1);
            split2(v1.x, v1.y, h2, l2); split2(v1.z, v1.w, h3, l3);
            uint32_t off = row * 256 + ((sch ^ (row & 7)) << 4);
            *(uint4*)(smem + OFF_KH + off) = make_uint4(h0, h1, h2, h3);
            *(uint4*)(smem + OFF_KL + off) = make_uint4(l0, l1, l2, l3);
        }
        if (tid < BN) ((float*)(smem + OFF_QB))[tid] = g_qbias[kbase + tid];
    }

    float O[16][4];
    float msc0 = 0.f, msc1 = 0.f;         /* static per-row scale (set at t=0) */
    float l0r = 0.f, l1r = 0.f;           /* per-thread partial l             */
    float pm0 = 0.f, pm1 = 0.f;           /* per-thread partial max-p         */
    #pragma unroll
    for (int nt = 0; nt < 16; ++nt)
        #pragma unroll
        for (int c = 0; c < 4; ++c) O[nt][c] = 0.f;

    const int b1_key = ((lane >> 4) << 3) + (lane & 7);
    const int b1_cs  = ((lane >> 3) & 1);
    const int b2_key = ((lane >> 3) & 1) * 8 + (lane & 7);
    const int b2_cs  = (lane >> 4);

    for (int t = 0; t < NTILES; ++t) {
        __syncthreads();   /* buf[t&1] ready; buf[(t+1)&1] free */
        const uint32_t bufR = (uint32_t)(t & 1) * BUF_STRIDE;
        const uint32_t bufW = (uint32_t)((t + 1) & 1) * BUF_STRIDE;
        const bool has_next = (t + 1 < NTILES);

        /* ---- stage fp32 loads of K tile t+1 (latency hidden under GEMM1) ---- */
        float4 sA[4], sB[4];
        float sqb = 0.f;
        if (has_next) {
            const int kb = split * KEYS_PER_SPLIT + (t + 1) * BN;
            #pragma unroll
            for (int i = 0; i < 4; ++i) {
                const float* src = qst + (size_t)(kb + srow + 16 * i) * D_DIM + sch * 8;
                sA[i] = *(const float4*)src;
                sB[i] = *(const float4*)(src + 4);
            }
            if (tid < BN) sqb = g_qbias[kb + tid];
        }

        /* ---- GEMM1: S = Qh*Kh + Ql*Kh + Qh*Kl (base-2 scaled) ---- */
        float S[8][4];
        #pragma unroll
        for (int nt = 0; nt < 8; ++nt)
            #pragma unroll
            for (int c = 0; c < 4; ++c) S[nt][c] = 0.f;

        #pragma unroll
        for (int kt = 0; kt < 8; ++kt) {
            uint32_t bh[4][4];
            #pragma unroll
            for (int np = 0; np < 4; ++np) {
                int key = np * 16 + b1_key;
                int ch  = kt * 2 + b1_cs;
                LDSM4(bh[np], sb + bufR + OFF_KH + key * 256 + ((ch ^ (key & 7)) << 4));
            }
            #pragma unroll
            for (int np = 0; np < 4; ++np) {
                MMA(S[2 * np],     aQh[kt], &bh[np][0]);
                MMA(S[2 * np + 1], aQh[kt], &bh[np][2]);
            }
            #pragma unroll
            for (int np = 0; np < 4; ++np) {
                MMA(S[2 * np],     aQl[kt], &bh[np][0]);
                MMA(S[2 * np + 1], aQl[kt], &bh[np][2]);
            }
            #pragma unroll
            for (int np = 0; np < 4; ++np) {   /* reuse regs for Kl */
                int key = np * 16 + b1_key;
                int ch  = kt * 2 + b1_cs;
                LDSM4(bh[np], sb + bufR + OFF_KL + key * 256 + ((ch ^ (key & 7)) << 4));
            }
            #pragma unroll
            for (int np = 0; np < 4; ++np) {
                MMA(S[2 * np],     aQh[kt], &bh[np][0]);
                MMA(S[2 * np + 1], aQh[kt], &bh[np][2]);
            }
        }

        /* ---- convert + store staged tile t+1 into the free buffer ---- */
        if (has_next) {
            #pragma unroll
            for (int i = 0; i < 4; ++i) {
                int row = srow + 16 * i;
                uint32_t h0, l0, h1, l1, h2, l2, h3, l3;
                split2(sA[i].x, sA[i].y, h0, l0); split2(sA[i].z, sA[i].w, h1, l1);
                split2(sB[i].x, sB[i].y, h2, l2); split2(sB[i].z, sB[i].w, h3, l3);
                uint32_t off = row * 256 + ((sch ^ (row & 7)) << 4);
                *(uint4*)(smem + bufW + OFF_KH + off) = make_uint4(h0, h1, h2, h3);
                *(uint4*)(smem + bufW + OFF_KL + off) = make_uint4(l0, l1, l2, l3);
            }
            if (tid < BN) ((float*)(smem + OFF_QB + ((t + 1) & 1) * 256))[tid] = sqb;
        }

        /* ---- static-scale softmax: no reductions, no rescale ---- */
        const float* qbp = (const float*)(smem + OFF_QB + (t & 1) * 256);
        uint32_t P[8][2];
        {
            #pragma unroll
            for (int nt = 0; nt < 8; ++nt) {
                float2 tq = *(const float2*)&qbp[nt * 8 + (lane & 3) * 2];
                S[nt][0] += tq.x; S[nt][1] += tq.y;
                S[nt][2] += tq.x; S[nt][3] += tq.y;
            }
            if (t == 0) {   /* one-time: m_scale = row max of tile 0 */
                float mx0 = -INFINITY, mx1 = -INFINITY;
                #pragma unroll
                for (int nt = 0; nt < 8; ++nt) {
                    mx0 = fmaxf(mx0, fmaxf(S[nt][0], S[nt][1]));
                    mx1 = fmaxf(mx1, fmaxf(S[nt][2], S[nt][3]));
                }
                mx0 = fmaxf(mx0, __shfl_xor_sync(0xffffffffu, mx0, 1));
                mx0 = fmaxf(mx0, __shfl_xor_sync(0xffffffffu, mx0, 2));
                mx1 = fmaxf(mx1, __shfl_xor_sync(0xffffffffu, mx1, 1));
                mx1 = fmaxf(mx1, __shfl_xor_sync(0xffffffffu, mx1, 2));
                msc0 = mx0; msc1 = mx1;
            }
            #pragma unroll
            for (int nt = 0; nt < 8; ++nt) {
                float p0 = ex2(S[nt][0] - msc0);
                float p1 = ex2(S[nt][1] - msc0);
                float p2 = ex2(S[nt][2] - msc1);
                float p3 = ex2(S[nt][3] - msc1);
                __nv_bfloat162 b01, b23;
                b01.x = __float2bfloat16(p0); b01.y = __float2bfloat16(p1);
                b23.x = __float2bfloat16(p2); b23.y = __float2bfloat16(p3);
                /* l and max-p from the ROUNDED P for O/l consistency */
                float q0 = __bfloat162float(b01.x), q1 = __bfloat162float(b01.y);
                float q2 = __bfloat162float(b23.x), q3 = __bfloat162float(b23.y);
                l0r += q0 + q1;  l1r += q2 + q3;
                pm0 = fmaxf(pm0, fmaxf(q0, q1));
                pm1 = fmaxf(pm1, fmaxf(q2, q3));
                P[nt][0] = *(uint32_t*)&b01;
                P[nt][1] = *(uint32_t*)&b23;
            }
        }

        /* ---- GEMM2: O += P * Vh ---- */
        #pragma unroll
        for (int kt2 = 0; kt2 < 4; ++kt2) {
            uint32_t aP[4] = { P[2 * kt2][0], P[2 * kt2][1],
                               P[2 * kt2 + 1][0], P[2 * kt2 + 1][1] };
            const int key = kt2 * 16 + b2_key;
            const uint32_t krow = sb + bufR + OFF_KH + key * 256;
            #pragma unroll
            for (int dp = 0; dp < 8; ++dp) {
                uint32_t bv[4];
                int ch = dp * 2 + b2_cs;
                LDSM4T(bv, krow + ((ch ^ (key & 7)) << 4));
                MMA(O[2 * dp],     aP, &bv[0]);
                MMA(O[2 * dp + 1], aP, &bv[2]);
            }
        }
    }

    /* ---- epilogue: one-time l / pm reductions, write O and (msc,pm,l) ---- */
    {
        l0r += __shfl_xor_sync(0xffffffffu, l0r, 1);
        l0r += __shfl_xor_sync(0xffffffffu, l0r, 2);
        l1r += __shfl_xor_sync(0xffffffffu, l1r, 1);
        l1r += __shfl_xor_sync(0xffffffffu, l1r, 2);
        pm0 = fmaxf(pm0, __shfl_xor_sync(0xffffffffu, pm0, 1));
        pm0 = fmaxf(pm0, __shfl_xor_sync(0xffffffffu, pm0, 2));
        pm1 = fmaxf(pm1, __shfl_xor_sync(0xffffffffu, pm1, 1));
        pm1 = fmaxf(pm1, __shfl_xor_sync(0xffffffffu, pm1, 2));

        int r1 = row0 + m0 + (lane >> 2);
        int r2 = r1 + 8;
        if ((lane & 3) == 0) {
            g_ml[(size_t)split * T_DIM + r1] = make_float4(msc0, pm0, l0r, 0.f);
            g_ml[(size_t)split * T_DIM + r2] = make_float4(msc1, pm1, l1r, 0.f);
        }
        float* o1 = g_O + ((size_t)split * T_DIM + r1) * D_DIM + (lane & 3) * 2;
        float* o2 = g_O + ((size_t)split * T_DIM + r2) * D_DIM + (lane & 3) * 2;
        #pragma unroll
        for (int nt = 0; nt < 16; ++nt) {
            *(float2*)(o1 + nt * 8) = make_float2(O[nt][0], O[nt][1]);
            *(float2*)(o2 + nt * 8) = make_float2(O[nt][2], O[nt][3]);
        }
    }
}

/* ============ K2: combine splits, write out cols [0,384), emit b ============ */
__global__ void combine_kernel(const float* __restrict__ x, float* __restrict__ out) {
    int row  = (blockIdx.x * blockDim.x + threadIdx.x) >> 5;
    int lane = threadIdx.x & 31;
    float4 ml[NSPLIT];
    float M = -INFINITY;
    #pragma unroll
    for (int s = 0; s < NSPLIT; ++s) {
        ml[s] = g_ml[(size_t)s * T_DIM + row];
        M = fmaxf(M, ml[s].x);
    }
    float L = 0.f, e[NSPLIT], bmax = 0.f;
    #pragma unroll
    for (int s = 0; s < NSPLIT; ++s) {
        e[s] = ex2(ml[s].x - M);
        L += ml[s].z * e[s];
        bmax = fmaxf(bmax, ml[s].y * e[s]);
    }
    float invL = 1.0f / L;
    float4 U = make_float4(0.f, 0.f, 0.f, 0.f);
    #pragma unroll
    for (int s = 0; s < NSPLIT; ++s) {
        float4 o = *(const float4*)&g_O[((size_t)s * T_DIM + row) * D_DIM + lane * 4];
        U.x += o.x * e[s]; U.y += o.y * e[s]; U.z += o.z * e[s]; U.w += o.w * e[s];
    }
    U.x *= invL; U.y *= invL; U.z *= invL; U.w *= invL;
    float4 c = *(const float4*)&x[(size_t)row * D_DIM + lane * 4];
    float* orow = out + (size_t)row * (4 * D_DIM);
    *(float4*)&orow[lane * 4]             = c;
    *(float4*)&orow[D_DIM + lane * 4]     = U;
    *(float4*)&orow[2 * D_DIM + lane * 4] = make_float4(c.x * U.x, c.y * U.y, c.z * U.z, c.w * U.w);
    if (lane == 0) g_b[row] = bmax * invL;   /* b = max_j A */
}

/* ============ K3/K4/K5: h = b @ context; out cols [384,512) = ctx*h ============ */
__global__ void hpart_kernel(const float* __restrict__ x) {
    int d = threadIdx.x;
    int r0 = blockIdx.x * 32;
    float s = 0.f;
    #pragma unroll 8
    for (int r = 0; r < 32; ++r)
        s += g_b[r0 + r] * x[(size_t)(r0 + r) * D_DIM + d];
    g_hpart[blockIdx.x * D_DIM + d] = s;
}
__global__ void hreduce_kernel() {
    int d = threadIdx.x;
    float s = 0.f;
    #pragma unroll 16
    for (int b = 0; b < 256; ++b) s += g_hpart[b * D_DIM + d];
    g_h[d] = s;
}
__global__ void hwrite_kernel(const float* __restrict__ x, float* __restrict__ out) {
    int idx = blockIdx.x * blockDim.x + threadIdx.x;
    int row = idx >> 5;
    int dq  = idx & 31;
    float4 c = ((const float4*)x)[(size_t)row * 32 + dq];
    float4 h = ((const float4*)g_h)[dq];
    ((float4*)out)[(size_t)row * 128 + 96 + dq] =
        make_float4(c.x * h.x, c.y * h.y, c.z * h.z, c.w * h.w);
}

/* ============================================================================ */
extern "C" void kernel_launch(void* const* d_in, const int* in_sizes, int n_in,
                              void* d_out, int out_size) {
    const float* x    = (const float*)d_in[0];
    const float* kern = (const float*)d_in[1];
    float* out = (float*)d_out;

    cudaFuncSetAttribute(flash_kernel, cudaFuncAttributeMaxDynamicSharedMemorySize, SMEM_SZ);

    qbias_kernel<<<T_DIM / 8, 256>>>(x, kern);
    flash_kernel<<<(T_DIM / BM) * NSPLIT, NTH, SMEM_SZ>>>(x, kern);
    combine_kernel<<<(T_DIM * 32) / 256, 256>>>(x, out);
    hpart_kernel<<<256, 128>>>(x);
    hreduce_kernel<<<1, 128>>>();
    hwrite_kernel<<<(T_DIM * D_DIM / 4) / 256, 256>>>(x, out);
}